// round 13
// baseline (speedup 1.0000x reference)
#include <cuda_runtime.h>
#include <stdint.h>

// KVCache_9526237462719:
//   input_pos: int32[S], k_val/v_val: f32[B,H,S,D], k_cache/v_cache: f32[B,H,BLOCK,D]
//   out = [k_cache.at[:,:,pos].set(k_val)[:,:,:S,:], same for v] concat, f32.
#define KB      4
#define KH      32
#define KS      1024
#define KD      128
#define KBLOCK  4096

#define D4      (KD / 4)                 // 32 float4 per row
#define HALF4   (4u * KH * KS * D4)      // 4,194,304 = 2^22
#define TOTAL4  (2u * HALF4)             // 8,388,608 = 2^23

#define NTHREADS 512
#define UNROLL   4
#define NBLOCKS  4096                    // 4096*512 = 2^21 threads
#define STRIDE   (1u << 21)              // UNROLL*STRIDE = TOTAL4

// Final recombination: R7 structure (best occupancy / cold time — hoisted
// addressing, UNROLL=4, probe-based inverse map, no smem/barriers) with the
// R12-winning cache policy (default loads AND default stores, maximizing
// cross-replay L2 reuse in the graph-replay timed regime).
__global__ __launch_bounds__(NTHREADS)
void kv_fused_kernel(const int*    __restrict__ input_pos,
                     const float4* __restrict__ k_val,
                     const float4* __restrict__ v_val,
                     const float4* __restrict__ k_cache,
                     const float4* __restrict__ v_cache,
                     float4*       __restrict__ out) {
    // i0 in [0, 2^21); slot u handles i = i0 + u*2^21.
    //   is_v = (u >= 2)            -- compile-time
    //   d4, p invariant across u   (2^21 is a multiple of S*D4 = 2^15)
    //   bh   = bh0 + (u&1)*64      (bh0 < 64)
    unsigned i0  = blockIdx.x * NTHREADS + threadIdx.x;
    unsigned d4  = i0 & (D4 - 1);
    unsigned r0  = i0 >> 5;
    unsigned p   = r0 & (KS - 1);
    unsigned bh0 = r0 >> 10;              // < 64

    // inv[p]: which source s wrote position p (−1 if none).
    int s;
    if (__ldg(input_pos + p) == (int)p) {
        s = (int)p;                       // fast path (always taken here)
    } else {
        s = -1;                           // general fallback: last writer wins
        for (int t = 0; t < KS; t++) {
            if (__ldg(input_pos + t) == (int)p) s = t;
        }
    }

    const float4* kbase;
    const float4* vbase;
    unsigned bstride;                     // float4s per bh step
    if (s >= 0) {
        kbase   = k_val + (unsigned)s * D4 + d4;
        vbase   = v_val + (unsigned)s * D4 + d4;
        bstride = KS * D4;                // 32768
    } else {
        kbase   = k_cache + p * D4 + d4;
        vbase   = v_cache + p * D4 + d4;
        bstride = KBLOCK * D4;            // 131072
    }

    // Default-policy loads and stores (cross-replay L2 reuse).
    float4 r[UNROLL];
    r[0] = kbase[(size_t)bh0 * bstride];
    r[1] = kbase[(size_t)(bh0 + 64u) * bstride];
    r[2] = vbase[(size_t)bh0 * bstride];
    r[3] = vbase[(size_t)(bh0 + 64u) * bstride];

    #pragma unroll
    for (int u = 0; u < UNROLL; u++) {
        out[i0 + u * STRIDE] = r[u];
    }
}

extern "C" void kernel_launch(void* const* d_in, const int* in_sizes, int n_in,
                              void* d_out, int out_size) {
    const int*    input_pos = (const int*)d_in[0];
    const float4* k_val     = (const float4*)d_in[1];
    const float4* v_val     = (const float4*)d_in[2];
    const float4* k_cache   = (const float4*)d_in[3];
    const float4* v_cache   = (const float4*)d_in[4];
    float4*       out       = (float4*)d_out;

    kv_fused_kernel<<<NBLOCKS, NTHREADS>>>(input_pos, k_val, v_val,
                                           k_cache, v_cache, out);
}